// round 16
// baseline (speedup 1.0000x reference)
#include <cuda_runtime.h>
#include <cstdint>
#include <math.h>

// ---------------- problem constants ----------------
#define BB   64
#define SS   512
#define DIN  64
#define HH   512
#define NLAY 4
#define DOUT 64

// ---------------- config ----------------
#define NB   128         // 32 blocks per layer
#define NT   320         // 8 consumer warps (2m x 2n x 2k) + 2 producer warps
#define BPL  32
#define UPB  16          // hidden units per block (64 gate rows)
#define KC   128         // K elements per chunk

// smem layout (phase 1), bytes
#define ROWB      272                 // bytes per operand row (256 data + 16 pad)
#define PLANE_B   17408               // 64 * 272
#define BUF_B     69632               // 4 planes: Ahi, Alo, Bhi, Blo
#define DS_OFF_F  34816               // float idx of Ds (byte 139264); 4 planes (2 slots x 2 wk)
#define DSPLANE_F 4352                // 64 * 68 floats per plane
#define DPITCH    68
#define PAD       68
#define MB_OFF    208896              // 8 mbarriers
#define SMEM_BYTES 208960

// ---------------- persistent device state ----------------
__device__ unsigned short g_Whi[NLAY][2048][1024];    // pre-split weights, block-row order
__device__ unsigned short g_Wlo[NLAY][2048][1024];    // unwritten k stays 0
__device__ unsigned short g_acthi[NLAY][2][BB][1024]; // per-layer B operand planes
__device__ unsigned short g_actlo[NLAY][2][BB][1024];
__device__ unsigned short g_xhi[SS][BB][DIN];         // pre-split input
__device__ unsigned short g_xlo[SS][BB][DIN];
__device__ float g_h3[(size_t)BB * SS * HH];          // layer-3 h for phase 2
__device__ int g_cnt[NLAY];                           // per-layer wave progress
__device__ unsigned int g_arrive = 0;
__device__ unsigned int g_gen    = 0;

// ---------------- helpers ----------------
__device__ __forceinline__ uint32_t smem_u32(const void* p) {
    uint32_t a;
    asm("{ .reg .u64 t; cvta.to.shared.u64 t, %1; cvt.u32.u64 %0, t; }" : "=r"(a) : "l"(p));
    return a;
}
__device__ __forceinline__ unsigned short bf16rn(float v) {
    uint32_t u = __float_as_uint(v);
    uint32_t r = u + 0x7FFFu + ((u >> 16) & 1u);
    return (unsigned short)(r >> 16);
}
__device__ __forceinline__ void split2(float v, unsigned short& h, unsigned short& l) {
    h = bf16rn(v);
    float hf = __uint_as_float((uint32_t)h << 16);
    l = bf16rn(v - hf);
}
__device__ __forceinline__ float fsig(float x)   { return __fdividef(1.0f, 1.0f + __expf(-x)); }
__device__ __forceinline__ float ftanh_(float x) { return __fdividef(2.0f, 1.0f + __expf(-2.0f * x)) - 1.0f; }

__device__ __forceinline__ void poll_ge(int* p, int v) {
    int x;
    while (true) {
        asm volatile("ld.global.acquire.gpu.b32 %0, [%1];" : "=r"(x) : "l"(p) : "memory");
        if (x >= v) return;
        __nanosleep(32);
    }
}

__device__ __forceinline__ void mma_bf16(float* c, const uint32_t* a, const uint32_t* b) {
    asm volatile(
        "mma.sync.aligned.m16n8k16.row.col.f32.bf16.bf16.f32 "
        "{%0,%1,%2,%3}, {%4,%5,%6,%7}, {%8,%9}, {%0,%1,%2,%3};"
        : "+f"(c[0]), "+f"(c[1]), "+f"(c[2]), "+f"(c[3])
        : "r"(a[0]), "r"(a[1]), "r"(a[2]), "r"(a[3]), "r"(b[0]), "r"(b[1]));
}
__device__ __forceinline__ void ldsm4(uint32_t* r, uint32_t saddr) {
    asm volatile("ldmatrix.sync.aligned.m8n8.x4.shared.b16 {%0,%1,%2,%3}, [%4];"
                 : "=r"(r[0]), "=r"(r[1]), "=r"(r[2]), "=r"(r[3]) : "r"(saddr));
}
__device__ __forceinline__ void cp16(uint32_t d, const void* s) {
    asm volatile("cp.async.cg.shared.global [%0], [%1], 16;" :: "r"(d), "l"(s) : "memory");
}

// ---- mbarrier primitives (baseline PTX, sm_80+) ----
#define MBINIT(addr, cnt) \
    asm volatile("mbarrier.init.shared::cta.b64 [%0], %1;" :: "r"(addr), "r"((uint32_t)(cnt)) : "memory")
#define MBARR(addr) \
    asm volatile("{\n\t.reg .b64 st;\n\tmbarrier.arrive.shared::cta.b64 st, [%0];\n\t}" \
                 :: "r"(addr) : "memory")
#define CPARRIVE(addr) \
    asm volatile("cp.async.mbarrier.arrive.noinc.shared::cta.b64 [%0];" :: "r"(addr) : "memory")
#define MBWAIT(addr, ph) do { \
    uint32_t done_; \
    do { \
        asm volatile("{\n\t.reg .pred p;\n\t" \
            "mbarrier.try_wait.parity.shared::cta.b64 p, [%1], %2;\n\t" \
            "selp.b32 %0, 1, 0, p;\n\t}" \
            : "=r"(done_) : "r"(addr), "r"((uint32_t)(ph)) : "memory"); \
    } while (!done_); \
} while (0)

#define BAR1() asm volatile("bar.sync 1, 256;" ::: "memory")   // consumers
#define BAR2() asm volatile("bar.sync 2, 64;"  ::: "memory")   // producers

__device__ __forceinline__ void gridbar(unsigned int& lgen) {
    __syncthreads();
    __threadfence();
    if (threadIdx.x == 0) {
        unsigned int old = atomicAdd(&g_arrive, 1u);
        if (((old + 1u) % NB) == 0u) {
            atomicAdd(&g_gen, 1u);
        } else {
            while (*((volatile unsigned int*)&g_gen) < lgen + 1u) { __nanosleep(32); }
        }
    }
    lgen += 1u;
    __syncthreads();
    __threadfence();
}

// ---- producer staging (64 threads, ptid in [0,64)) ----
__device__ __forceinline__ void stageA64(uint32_t smb, int buf, int ch, int layer,
                                         int blk, int ptid) {
    const uint32_t base = smb + (uint32_t)buf * BUF_B;
    #pragma unroll
    for (int j = 0; j < 16; ++j) {
        const int idx = ptid + 64 * j, row = idx >> 4, q = idx & 15;
        const uint32_t d = base + (uint32_t)(row * ROWB + q * 16);
        const int k = ch * KC + q * 8;
        cp16(d,           &g_Whi[layer][blk * 64 + row][k]);
        cp16(d + PLANE_B, &g_Wlo[layer][blk * 64 + row][k]);
    }
}
__device__ __forceinline__ void stageB64(uint32_t smb, int buf, int ch, int layer,
                                         int t, int Kin, int ptid) {
    const uint32_t base = smb + (uint32_t)buf * BUF_B;
    #pragma unroll
    for (int j = 0; j < 16; ++j) {
        const int idx = ptid + 64 * j, n = idx >> 4, q = idx & 15;
        const uint32_t d = base + 2u * PLANE_B + (uint32_t)(n * ROWB + q * 16);
        const int k = ch * KC + q * 8;
        const unsigned short *sh, *sl;
        if (layer == 0 && k < DIN) {
            sh = &g_xhi[t][n][k];
            sl = &g_xlo[t][n][k];
        } else {
            const int slot = (k < Kin) ? (t & 1) : ((t & 1) ^ 1);
            sh = &g_acthi[layer][slot][n][k];
            sl = &g_actlo[layer][slot][n][k];
        }
        cp16(d, sh);
        cp16(d + PLANE_B, sl);
    }
}

__global__ void __launch_bounds__(NT, 1) lstm_mma_kernel(
    const float* __restrict__ x,
    const float* __restrict__ W0, const float* __restrict__ b0,
    const float* __restrict__ W1, const float* __restrict__ b1,
    const float* __restrict__ W2, const float* __restrict__ b2,
    const float* __restrict__ W3, const float* __restrict__ b3,
    const float* __restrict__ lng, const float* __restrict__ lnb,
    const float* __restrict__ Wo,  const float* __restrict__ bo,
    float* __restrict__ out)
{
    extern __shared__ char smc[];
    float* smf = (float*)smc;
    const int tid = threadIdx.x;
    const int bx  = blockIdx.x;
    unsigned int lgen = *((volatile unsigned int*)&g_gen);
    const uint32_t smb = smem_u32(smc);
    const uint32_t mbF0 = smb + MB_OFF,      mbF1 = smb + MB_OFF + 8;
    const uint32_t mbE0 = smb + MB_OFF + 16, mbE1 = smb + MB_OFF + 24;
    const uint32_t mbDF0 = smb + MB_OFF + 32, mbDF1 = smb + MB_OFF + 40;
    const uint32_t mbDE0 = smb + MB_OFF + 48, mbDE1 = smb + MB_OFF + 56;

    const float* Wsrc[4] = {W0, W1, W2, W3};
    const float* bsrc[4] = {b0, b1, b2, b3};

    // ---------------- phase 0: reset, init mbarriers, split W and x ----------
    if (tid == 0) {
        MBINIT(mbF0, 64); MBINIT(mbF1, 64);   // producer cp-arrivals (.noinc)
        MBINIT(mbE0, 8);  MBINIT(mbE1, 8);    // consumer warp arrivals
        MBINIT(mbDF0, 8); MBINIT(mbDF1, 8);   // Ds full (consumer warps)
        MBINIT(mbDE0, 1); MBINIT(mbDE1, 1);   // Ds empty (producer ptid0)
    }
    if (bx == 0 && tid < 4) g_cnt[tid] = 0;
    {
        uint4 z = make_uint4(0, 0, 0, 0);
        uint4* ph = (uint4*)&g_acthi[0][0][0][0];
        uint4* pl = (uint4*)&g_actlo[0][0][0][0];
        const int n16 = NLAY * 2 * BB * 1024 * 2 / 16;
        for (int i = bx * NT + tid; i < n16; i += NB * NT) { ph[i] = z; pl[i] = z; }
    }
    {
        for (int rr = 0; rr < 64; ++rr) {
            const int gr = bx * 64 + rr;
            const int l = gr >> 11, r = gr & 2047;
            const int blk2 = r >> 6, rloc = r & 63, iu = rloc >> 2, g = rloc & 3;
            const int fanin = (l == 0) ? (DIN + HH) : (2 * HH);
            const float* src = Wsrc[l] + (size_t)(g * HH + blk2 * UPB + iu) * fanin;
            const int k = tid * 4;
            if (k < fanin) {
                float4 v = __ldg((const float4*)(src + k));
                unsigned short h0, l0, h1, l1, h2, l2, h3, l3;
                split2(v.x, h0, l0); split2(v.y, h1, l1);
                split2(v.z, h2, l2); split2(v.w, h3, l3);
                const int kk = (l == 0 && k >= DIN) ? k + 64 : k;
                *(uint2*)&g_Whi[l][r][kk] =
                    make_uint2((uint32_t)h0 | ((uint32_t)h1 << 16), (uint32_t)h2 | ((uint32_t)h3 << 16));
                *(uint2*)&g_Wlo[l][r][kk] =
                    make_uint2((uint32_t)l0 | ((uint32_t)l1 << 16), (uint32_t)l2 | ((uint32_t)l3 << 16));
            }
        }
    }
    {
        for (int i = bx * NT + tid; i < SS * BB * (DIN / 2); i += NB * NT) {
            const int k2 = i & 31, n = (i >> 5) & 63, tt = i >> 11;
            float2 v = __ldg((const float2*)&x[((size_t)n * SS + tt) * DIN + k2 * 2]);
            unsigned short h0, l0, h1, l1;
            split2(v.x, h0, l0); split2(v.y, h1, l1);
            *(uint32_t*)&g_xhi[tt][n][k2 * 2] = (uint32_t)h0 | ((uint32_t)h1 << 16);
            *(uint32_t*)&g_xlo[tt][n][k2 * 2] = (uint32_t)l0 | ((uint32_t)l1 << 16);
        }
    }
    gridbar(lgen);

    // ---------------- phase 1: pipelined producer/consumer wavefront ----------
    const int layer = bx >> 5;
    const int blk   = bx & 31;
    const int u0    = blk * UPB;
    const float* bl = bsrc[layer];
    const int Kin   = (layer == 0) ? DIN : HH;
    const int kst   = (layer == 0) ? 128 : 512;   // own-h store offset
    const int nch   = (layer == 0) ? 5 : 8;
    const int ownStart = (layer == 0) ? 1 : 4;    // first chunk touching own h(t-1)

    const int lane = tid & 31, wid = tid >> 5;

    if (wid < 8) {
        // =================== CONSUMERS (8 warps): pure chunk stream ==========
        const int wm = wid & 1, wn = (wid >> 1) & 1, wk = wid >> 2;

        const uint32_t aoff0 = (uint32_t)((wm * 32 + (lane & 15)) * ROWB + (lane >> 4) * 16);
        const uint32_t aoff1 = aoff0 + 16u * ROWB;
        const uint32_t boff0 = 2u * PLANE_B +
            (uint32_t)((wn * 32 + (lane & 7) + ((lane >> 4) << 3)) * ROWB + (((lane >> 3) & 1) << 4));
        const uint32_t boff1 = boff0 + 16u * ROWB;
        const uint32_t ksb0 = (uint32_t)(wk * 4) * 32u;

        float* Ds = smf + DS_OFF_F;
        int cg = 0;

        for (int t = 0; t < SS; ++t) {
            float acc[2][4][4];
            #pragma unroll
            for (int mt = 0; mt < 2; ++mt)
                #pragma unroll
                for (int nt = 0; nt < 4; ++nt)
                    #pragma unroll
                    for (int q = 0; q < 4; ++q) acc[mt][nt][q] = 0.f;

            for (int ch = 0; ch < nch; ++ch) {
                const int b = cg & 1, ph = (cg >> 1) & 1;
                MBWAIT((b ? mbF1 : mbF0), ph);

                const uint32_t bb = smb + (uint32_t)b * BUF_B;
                #pragma unroll
                for (int ks0 = 0; ks0 < 4; ++ks0) {
                    const uint32_t kb = ksb0 + (uint32_t)ks0 * 32u;
                    uint32_t ah0[4], ah1[4], al0[4], al1[4];
                    uint32_t bh0[4], bh1[4], bl0[4], bl1[4];
                    ldsm4(ah0, bb + aoff0 + kb);
                    ldsm4(ah1, bb + aoff1 + kb);
                    ldsm4(al0, bb + aoff0 + PLANE_B + kb);
                    ldsm4(al1, bb + aoff1 + PLANE_B + kb);
                    ldsm4(bh0, bb + boff0 + kb);
                    ldsm4(bh1, bb + boff1 + kb);
                    ldsm4(bl0, bb + boff0 + PLANE_B + kb);
                    ldsm4(bl1, bb + boff1 + PLANE_B + kb);
                    const uint32_t* bhv[4] = {bh0, bh0 + 2, bh1, bh1 + 2};
                    const uint32_t* blv[4] = {bl0, bl0 + 2, bl1, bl1 + 2};
                    #pragma unroll
                    for (int nt = 0; nt < 4; ++nt) {
                        mma_bf16(acc[0][nt], ah0, bhv[nt]);
                        mma_bf16(acc[0][nt], ah0, blv[nt]);
                        mma_bf16(acc[0][nt], al0, bhv[nt]);
                        mma_bf16(acc[1][nt], ah1, bhv[nt]);
                        mma_bf16(acc[1][nt], ah1, blv[nt]);
                        mma_bf16(acc[1][nt], al1, bhv[nt]);
                    }
                }
                if (lane == 0) MBARR((b ? mbE1 : mbE0));
                ++cg;
            }

            // Ds write (parity-double-buffered); wait until producers drained t-2
            const int st = t & 1;
            if (t >= 2) MBWAIT((st ? mbDE1 : mbDE0), ((t >> 1) & 1) ^ 1);
            {
                float* Dp = Ds + st * (2 * DSPLANE_F) + wk * DSPLANE_F;
                const int r = lane >> 2, cp2 = (lane & 3) * 2;
                #pragma unroll
                for (int mt = 0; mt < 2; ++mt)
                    #pragma unroll
                    for (int nt = 0; nt < 4; ++nt) {
                        const int row = wm * 32 + mt * 16 + r;
                        const int col = wn * 32 + nt * 8 + cp2;
                        *(float2*)&Dp[row * DPITCH + col] =
                            make_float2(acc[mt][nt][0], acc[mt][nt][1]);
                        *(float2*)&Dp[(row + 8) * DPITCH + col] =
                            make_float2(acc[mt][nt][2], acc[mt][nt][3]);
                    }
            }
            if (lane == 0) MBARR((st ? mbDF1 : mbDF0));
        }
    } else {
        // =================== PRODUCERS (2 warps): stage + epilogue ===========
        const int ptid = tid - 256;               // 0..63
        const int pu   = ptid & 15;               // unit 0..15
        const int pb0  = (ptid >> 4) * 16;        // batch base (16 each)
        const float bzi = __ldg(&bl[0 * HH + u0 + pu]);
        const float bzf = __ldg(&bl[1 * HH + u0 + pu]);
        const float bzg = __ldg(&bl[2 * HH + u0 + pu]);
        const float bzo = __ldg(&bl[3 * HH + u0 + pu]);
        float c_st[16];
        #pragma unroll
        for (int j = 0; j < 16; ++j) c_st[j] = 0.f;
        float* Ds = smf + DS_OFF_F;
        int pg = 0;

        // prologue: input chunks of step 0
        if (ptid == 0 && layer > 0) poll_ge(&g_cnt[layer - 1], BPL * 1);
        BAR2();
        for (int ch = 0; ch < ownStart; ++ch) {
            const int b = pg & 1, eph = (((pg >> 1) & 1) ^ 1);
            MBWAIT((b ? mbE1 : mbE0), eph);
            stageA64(smb, b, ch, layer, blk, ptid);
            stageB64(smb, b, ch, layer, 0, Kin, ptid);
            CPARRIVE((b ? mbF1 : mbF0));
            ++pg;
        }

        for (int t = 0; t < SS; ++t) {
            // own-h chunks of step t (need sibling h(t-1))
            if (ptid == 0 && t > 0) poll_ge(&g_cnt[layer], BPL * t);
            BAR2();
            for (int ch = ownStart; ch < nch; ++ch) {
                const int b = pg & 1, eph = (((pg >> 1) & 1) ^ 1);
                MBWAIT((b ? mbE1 : mbE0), eph);
                stageA64(smb, b, ch, layer, blk, ptid);
                stageB64(smb, b, ch, layer, t, Kin, ptid);
                CPARRIVE((b ? mbF1 : mbF0));
                ++pg;
            }
            // pre-stage input chunks of step t+1 (overlaps epilogue below)
            if (t + 1 < SS) {
                if (ptid == 0 && layer > 0) poll_ge(&g_cnt[layer - 1], BPL * (t + 2));
                BAR2();
                for (int ch = 0; ch < ownStart; ++ch) {
                    const int b = pg & 1, eph = (((pg >> 1) & 1) ^ 1);
                    MBWAIT((b ? mbE1 : mbE0), eph);
                    stageA64(smb, b, ch, layer, blk, ptid);
                    stageB64(smb, b, ch, layer, t + 1, Kin, ptid);
                    CPARRIVE((b ? mbF1 : mbF0));
                    ++pg;
                }
            }

            // ---- epilogue of step t ----
            const int st = t & 1;
            MBWAIT((st ? mbDF1 : mbDF0), (t >> 1) & 1);
            if (ptid == 0 && layer < 3 && t >= 2) poll_ge(&g_cnt[layer + 1], BPL * (t - 2));
            BAR2();
            {
                const float* D0 = Ds + st * (2 * DSPLANE_F);
                const float* D1 = D0 + DSPLANE_F;
                #pragma unroll 4
                for (int j = 0; j < 16; ++j) {
                    const int b2 = pb0 + j;
                    const float zi = bzi + D0[(pu * 4 + 0) * DPITCH + b2] + D1[(pu * 4 + 0) * DPITCH + b2];
                    const float zf = bzf + D0[(pu * 4 + 1) * DPITCH + b2] + D1[(pu * 4 + 1) * DPITCH + b2];
                    const float zg = bzg + D0[(pu * 4 + 2) * DPITCH + b2] + D1[(pu * 4 + 2) * DPITCH + b2];
                    const float zo = bzo + D0[(pu * 4 + 3) * DPITCH + b2] + D1[(pu * 4 + 3) * DPITCH + b2];
                    const float c = fsig(zf) * c_st[j] + fsig(zi) * ftanh_(zg);
                    c_st[j] = c;
                    const float h = fsig(zo) * ftanh_(c);
                    unsigned short hh, hl;
                    split2(h, hh, hl);
                    g_acthi[layer][st][b2][kst + u0 + pu] = hh;
                    g_actlo[layer][st][b2][kst + u0 + pu] = hl;
                    if (layer < 3) {
                        g_acthi[layer + 1][st][b2][u0 + pu] = hh;
                        g_actlo[layer + 1][st][b2][u0 + pu] = hl;
                    } else {
                        g_h3[((size_t)b2 * SS + t) * HH + u0 + pu] = h;
                    }
                }
            }
            BAR2();
            if (ptid == 0) {
                __threadfence();
                atomicAdd(&g_cnt[layer], 1);
                MBARR((st ? mbDE1 : mbDE0));
            }
        }
    }

    // ---------------- phase 2: LayerNorm + output projection (consumers) ------
    if (tid < 256) {
        if (tid == 0) poll_ge(&g_cnt[3], BPL * SS);
        BAR1();

        float* As3 = smf;
        float* Ws3 = smf + 512 * PAD;
        float* red = smf + 512 * PAD + 64 * PAD;
        const int lane2 = tid & 31, wrp = tid >> 5;
        const int tc  = tid & 15, tr = tid >> 4;
        const int lkk = tid & 63, lr0 = tid >> 6;

        for (int i = 0; i < 4; ++i) {
            const int base_row = bx * 256 + i * 64;

            for (int rr = 0; rr < 64; ++rr) {
                const size_t row = (size_t)base_row + rr;
                const float v0 = __ldcg(&g_h3[row * HH + tid]);
                const float v1 = __ldcg(&g_h3[row * HH + tid + 256]);
                float s = v0 + v1, s2 = v0 * v0 + v1 * v1;
                #pragma unroll
                for (int off = 16; off > 0; off >>= 1) {
                    s  += __shfl_down_sync(0xffffffffu, s,  off);
                    s2 += __shfl_down_sync(0xffffffffu, s2, off);
                }
                if (lane2 == 0) { red[wrp] = s; red[8 + wrp] = s2; }
                BAR1();
                if (tid == 0) {
                    float S1 = 0.f, S2 = 0.f;
                    for (int jj = 0; jj < 8; ++jj) { S1 += red[jj]; S2 += red[8 + jj]; }
                    const float mu  = S1 * (1.0f / 512.0f);
                    const float var = S2 * (1.0f / 512.0f) - mu * mu;
                    red[16] = mu;
                    red[17] = rsqrtf(var + 1e-5f);
                }
                BAR1();
                const float mu = red[16], rstd = red[17];
                As3[tid * PAD + rr]         = (v0 - mu) * rstd * lng[tid]       + lnb[tid];
                As3[(tid + 256) * PAD + rr] = (v1 - mu) * rstd * lng[tid + 256] + lnb[tid + 256];
                BAR1();
            }

            float acc2[4][4];
            #pragma unroll
            for (int r = 0; r < 4; ++r)
                #pragma unroll
                for (int g = 0; g < 4; ++g) acc2[r][g] = 0.0f;

            for (int ch = 0; ch < 8; ++ch) {
                #pragma unroll
                for (int p = 0; p < 16; ++p) {
                    const int jc = p * 4 + lr0;
                    Ws3[lkk * PAD + (jc & 15) * 4 + (jc >> 4)] =
                        Wo[(size_t)jc * HH + ch * 64 + lkk];
                }
                BAR1();
                #pragma unroll 16
                for (int kk = 0; kk < 64; ++kk) {
                    const float4 a  = *(const float4*)(As3 + (ch * 64 + kk) * PAD + tr * 4);
                    const float4 wv = *(const float4*)(Ws3 + kk * PAD + tc * 4);
                    acc2[0][0] += a.x * wv.x; acc2[0][1] += a.x * wv.y;
                    acc2[0][2] += a.x * wv.z; acc2[0][3] += a.x * wv.w;
                    acc2[1][0] += a.y * wv.x; acc2[1][1] += a.y * wv.y;
                    acc2[1][2] += a.y * wv.z; acc2[1][3] += a.y * wv.w;
                    acc2[2][0] += a.z * wv.x; acc2[2][1] += a.z * wv.y;
                    acc2[2][2] += a.z * wv.z; acc2[2][3] += a.z * wv.w;
                    acc2[3][0] += a.w * wv.x; acc2[3][1] += a.w * wv.y;
                    acc2[3][2] += a.w * wv.z; acc2[3][3] += a.w * wv.w;
                }
                BAR1();
            }

            #pragma unroll
            for (int r = 0; r < 4; ++r) {
                const size_t row = (size_t)base_row + tr * 4 + r;
                #pragma unroll
                for (int g = 0; g < 4; ++g) {
                    const int d = g * 16 + tc;
                    out[row * DOUT + d] = acc2[r][g] + bo[d];
                }
            }
            BAR1();
        }
    }
}

extern "C" void kernel_launch(void* const* d_in, const int* in_sizes, int n_in,
                              void* d_out, int out_size) {
    const float* x   = (const float*)d_in[0];
    const float* W0  = (const float*)d_in[1];
    const float* b0  = (const float*)d_in[2];
    const float* W1  = (const float*)d_in[3];
    const float* b1  = (const float*)d_in[4];
    const float* W2  = (const float*)d_in[5];
    const float* b2  = (const float*)d_in[6];
    const float* W3  = (const float*)d_in[7];
    const float* b3  = (const float*)d_in[8];
    const float* lng = (const float*)d_in[9];
    const float* lnb = (const float*)d_in[10];
    const float* Wo  = (const float*)d_in[11];
    const float* bo  = (const float*)d_in[12];
    float* out = (float*)d_out;

    cudaFuncSetAttribute(lstm_mma_kernel,
                         cudaFuncAttributeMaxDynamicSharedMemorySize, SMEM_BYTES);
    lstm_mma_kernel<<<NB, NT, SMEM_BYTES>>>(
        x, W0, b0, W1, b1, W2, b2, W3, b3, lng, lnb, Wo, bo, out);
}